// round 10
// baseline (speedup 1.0000x reference)
#include <cuda_runtime.h>
#include <cuda_bf16.h>
#include <cstdint>

// ============================================================================
// sim = clamp(xn @ xn.T, 0), xn = row-normalized features (8192 x 256 fp32)
//
// sm_100 (no 'a') -> mma.sync.m16n8k16 bf16 + cp.async + ldmatrix.
// bf16 split, symmetric K-tripling: A=[hi|lo|hi], B=[hi|hi|lo] (K=768).
// R8 = R7 (128x128 CTA, 4 warps of 64x64, 2 CTAs/SM) plus:
//   - ONE __syncthreads per chunk (issue(kc+2) moved before compute; with 3
//     stages it writes the stage whose readers all passed the top barrier)
//   - software-pipelined ldmatrix fragments (double buffer across s-steps)
// ============================================================================

#define NROWS  8192
#define DIM    256
#define KCH    64            // bf16 per K-chunk (128 B rows)
#define NCHUNK 12            // virtual K = 768
#define TILE   128

__device__ __align__(128) __nv_bfloat16 g_X[(size_t)NROWS * 512];

// ---------------------------------------------------------------------------
__device__ __forceinline__ uint32_t smem_u32(const void* p) {
    uint32_t a;
    asm("{ .reg .u64 t; cvta.to.shared.u64 t, %1; cvt.u32.u64 %0, t; }"
        : "=r"(a) : "l"(p));
    return a;
}

#define CP_ASYNC_16(dst, src) \
    asm volatile("cp.async.cg.shared.global [%0], [%1], 16;" \
                 :: "r"(dst), "l"(src) : "memory")
#define CP_ASYNC_COMMIT() \
    asm volatile("cp.async.commit_group;" ::: "memory")
#define CP_ASYNC_WAIT(n) \
    asm volatile("cp.async.wait_group %0;" :: "n"(n) : "memory")

__device__ __forceinline__ void ldsm4(uint32_t* r, uint32_t addr) {
    asm volatile("ldmatrix.sync.aligned.m8n8.x4.shared.b16 {%0,%1,%2,%3}, [%4];"
                 : "=r"(r[0]), "=r"(r[1]), "=r"(r[2]), "=r"(r[3]) : "r"(addr));
}

__device__ __forceinline__ void mma16816(float* d, const uint32_t* a,
                                         const uint32_t* b) {
    asm volatile(
        "mma.sync.aligned.m16n8k16.row.col.f32.bf16.bf16.f32 "
        "{%0,%1,%2,%3}, {%4,%5,%6,%7}, {%8,%9}, {%0,%1,%2,%3};"
        : "+f"(d[0]), "+f"(d[1]), "+f"(d[2]), "+f"(d[3])
        : "r"(a[0]), "r"(a[1]), "r"(a[2]), "r"(a[3]), "r"(b[0]), "r"(b[1]));
}

// ---------------------------------------------------------------------------
// Kernel 1: normalize rows, emit bf16 split [hi | lo].
// ---------------------------------------------------------------------------
__global__ void __launch_bounds__(256)
norm_split_kernel(const float* __restrict__ feats)
{
    const int row  = blockIdx.x * 8 + (threadIdx.x >> 5);
    const int lane = threadIdx.x & 31;

    const float4* src = reinterpret_cast<const float4*>(feats + (size_t)row * DIM);
    float4 v0 = src[lane * 2];
    float4 v1 = src[lane * 2 + 1];

    float ss = v0.x * v0.x + v0.y * v0.y + v0.z * v0.z + v0.w * v0.w
             + v1.x * v1.x + v1.y * v1.y + v1.z * v1.z + v1.w * v1.w;
    #pragma unroll
    for (int o = 16; o; o >>= 1)
        ss += __shfl_xor_sync(0xFFFFFFFFu, ss, o);

    const float inv = 1.0f / fmaxf(sqrtf(ss), 1e-8f);

    float vals[8] = {v0.x, v0.y, v0.z, v0.w, v1.x, v1.y, v1.z, v1.w};
    const size_t base = (size_t)row * 512;
    #pragma unroll
    for (int j = 0; j < 8; ++j) {
        const int c = lane * 8 + j;
        float xn = vals[j] * inv;
        __nv_bfloat16 hi = __float2bfloat16(xn);
        __nv_bfloat16 lo = __float2bfloat16(xn - __bfloat162float(hi));
        g_X[base + c]       = hi;
        g_X[base + 256 + c] = lo;
    }
}

// ---------------------------------------------------------------------------
// Kernel 2: 128x128 CTA tile, 4 warps (64x64 each, 2x2), 3 stages, 128 thr.
// smem per stage 32 KB; x3 = 96 KB. Mirror buffer 66 KB reuses stage smem.
// 2 CTAs/SM (192 KB smem, <=255 regs/thread via launch_bounds(128,2)).
// ---------------------------------------------------------------------------
#define SMEM_STAGE_SZ 32768
#define SMEM_B_OFF    16384
#define SMEM_TOTAL    98304

__global__ void __launch_bounds__(128, 2)
cosine_gemm_kernel(float* __restrict__ out)
{
    extern __shared__ char smem[];
    const uint32_t sbase = smem_u32(smem);
    const int tid  = threadIdx.x;
    const int lane = tid & 31;
    const int wid  = tid >> 5;       // 0..3

    // Triangular tile decode: t -> (by, bx), bx <= by
    const int t = blockIdx.x;
    int by = (int)((sqrtf(8.0f * (float)t + 1.0f) - 1.0f) * 0.5f);
    while ((by + 1) * (by + 2) / 2 <= t) ++by;
    while (by * (by + 1) / 2 > t) --by;
    const int bx = t - by * (by + 1) / 2;

    const int rowbase = by * TILE;   // M rows (A operand)
    const int colbase = bx * TILE;   // N cols (B operand)

    const int wm = (wid >> 1) * 64;  // warp tile origin in M (0, 64)
    const int wn = (wid & 1) * 64;   // warp tile origin in N (0, 64)

    // --- cp.async loader: A 8 + B 8 groups of 16B per thread -------------
    const int lr = tid >> 3;         // 0..15
    const int lc = tid & 7;          // 0..7

    auto issue = [&](int kc) {
        const int ka = (kc < 8) ? kc : kc - 8;   // A: [hi | lo | hi]
        const int kb = (kc < 4) ? kc : kc - 4;   // B: [hi | hi | lo]
        const uint32_t stg = (uint32_t)(kc % 3) * SMEM_STAGE_SZ;
        #pragma unroll
        for (int p = 0; p < 8; ++p) {
            const int row = p * 16 + lr;
            const uint32_t swc = (uint32_t)((lc ^ (row & 7)) * 16);
            CP_ASYNC_16(sbase + stg + row * 128 + swc,
                &g_X[(size_t)(rowbase + row) * 512 + ka * KCH + lc * 8]);
            CP_ASYNC_16(sbase + stg + SMEM_B_OFF + row * 128 + swc,
                &g_X[(size_t)(colbase + row) * 512 + kb * KCH + lc * 8]);
        }
        CP_ASYNC_COMMIT();
    };

    // Fragment loaders (one s-step worth).
    auto load_afr = [&](uint32_t aB, int s, uint32_t (*afr)[4]) {
        #pragma unroll
        for (int i = 0; i < 4; ++i) {
            const int row = wm + 16 * i + (lane & 15);
            const int ch  = s * 2 + (lane >> 4);
            ldsm4(afr[i], aB + row * 128 + ((ch ^ (row & 7)) * 16));
        }
    };
    auto load_bfr = [&](uint32_t bB, int s, uint32_t (*bfr)[4]) {
        #pragma unroll
        for (int jj = 0; jj < 4; ++jj) {
            const int row = wn + 16 * jj + ((lane >> 4) << 3) + (lane & 7);
            const int ch  = s * 2 + ((lane >> 3) & 1);
            ldsm4(bfr[jj], bB + row * 128 + ((ch ^ (row & 7)) * 16));
        }
    };

    float acc[4][8][4];
    #pragma unroll
    for (int i = 0; i < 4; ++i)
        #pragma unroll
        for (int j = 0; j < 8; ++j)
            #pragma unroll
            for (int r = 0; r < 4; ++r)
                acc[i][j][r] = 0.0f;

    uint32_t afr[2][4][4];
    uint32_t bfr[2][4][4];

    issue(0);
    issue(1);

    for (int kc = 0; kc < NCHUNK; ++kc) {
        if (kc == NCHUNK - 1) { CP_ASYNC_WAIT(0); } else { CP_ASYNC_WAIT(1); }
        __syncthreads();
        // Stage (kc+2)%3 == (kc-1)%3: its readers all passed the barrier
        // above, so overwriting it now is WAR-safe. Loads overlap compute.
        if (kc + 2 < NCHUNK) issue(kc + 2);

        const uint32_t aB = sbase + (uint32_t)(kc % 3) * SMEM_STAGE_SZ;
        const uint32_t bB = aB + SMEM_B_OFF;

        // Software-pipelined fragments: load s+1 while computing s.
        load_afr(aB, 0, afr[0]);
        load_bfr(bB, 0, bfr[0]);
        #pragma unroll
        for (int s = 0; s < 4; ++s) {
            if (s < 3) {
                load_afr(aB, s + 1, afr[(s + 1) & 1]);
                load_bfr(bB, s + 1, bfr[(s + 1) & 1]);
            }
            #pragma unroll
            for (int i = 0; i < 4; ++i)
                #pragma unroll
                for (int j = 0; j < 8; ++j)
                    mma16816(acc[i][j], afr[s & 1][i],
                             &bfr[s & 1][j >> 1][(j & 1) * 2]);
        }
        // No second barrier: next iteration's top barrier provides it.
    }

    // --- Epilogue ---------------------------------------------------------
    const int grp = lane >> 2;       // 0..7
    const int t4  = lane & 3;        // 0..3

    // Direct write from registers (float2 = full 32B sector per quad).
    #pragma unroll
    for (int i = 0; i < 4; ++i) {
        #pragma unroll
        for (int j = 0; j < 8; ++j) {
            const size_t gr = (size_t)(rowbase + wm + 16 * i + grp);
            const size_t gc = (size_t)(colbase + wn + 8 * j + t4 * 2);
            float2 v01 = make_float2(fmaxf(acc[i][j][0], 0.0f),
                                     fmaxf(acc[i][j][1], 0.0f));
            float2 v23 = make_float2(fmaxf(acc[i][j][2], 0.0f),
                                     fmaxf(acc[i][j][3], 0.0f));
            *reinterpret_cast<float2*>(&out[gr * NROWS + gc]) = v01;
            *reinterpret_cast<float2*>(&out[(gr + 8) * NROWS + gc]) = v23;
        }
    }

    // Mirror write via smem transpose (skip on diagonal tiles).
    if (bx != by) {
        float* ctile = reinterpret_cast<float*>(smem);   // [128][129]
        __syncthreads();   // mainloop smem reads complete
        #pragma unroll
        for (int i = 0; i < 4; ++i) {
            #pragma unroll
            for (int j = 0; j < 8; ++j) {
                const int m = wm + 16 * i + grp;
                const int n = wn + 8 * j + t4 * 2;
                ctile[m * 129 + n]           = fmaxf(acc[i][j][0], 0.0f);
                ctile[m * 129 + n + 1]       = fmaxf(acc[i][j][1], 0.0f);
                ctile[(m + 8) * 129 + n]     = fmaxf(acc[i][j][2], 0.0f);
                ctile[(m + 8) * 129 + n + 1] = fmaxf(acc[i][j][3], 0.0f);
            }
        }
        __syncthreads();
        // warp w: n = w*32 .. w*32+31 ; stride-129 column reads conflict-free
        #pragma unroll
        for (int rr = 0; rr < 32; ++rr) {
            const int n = wid * 32 + rr;
            #pragma unroll
            for (int q = 0; q < 4; ++q) {
                const int m = q * 32 + lane;
                out[(size_t)(colbase + n) * NROWS + rowbase + m] =
                    ctile[m * 129 + n];
            }
        }
    }
}

// ---------------------------------------------------------------------------
extern "C" void kernel_launch(void* const* d_in, const int* in_sizes, int n_in,
                              void* d_out, int out_size)
{
    const float* feats = (const float*)d_in[0];
    float* out = (float*)d_out;
    (void)in_sizes; (void)n_in; (void)out_size;

    cudaFuncSetAttribute(cosine_gemm_kernel,
                         cudaFuncAttributeMaxDynamicSharedMemorySize,
                         SMEM_TOTAL);

    norm_split_kernel<<<NROWS / 8, 256>>>(feats);

    const int ntiles = (NROWS / TILE) * (NROWS / TILE + 1) / 2;   // 2080
    cosine_gemm_kernel<<<ntiles, 128, SMEM_TOTAL>>>(out);
}

// round 11
// speedup vs baseline: 1.8711x; 1.8711x over previous
#include <cuda_runtime.h>
#include <cuda_fp16.h>
#include <cstdint>

// ============================================================================
// sim = clamp(xn @ xn.T, 0), xn = row-normalized features (8192 x 256 fp32)
//
// sm_100 SIMT mma path is MAC-rate capped (~0.22 HMMA.16816/cyc/SM, measured
// invariant across schedules). Only lever: fewer MACs.
// R11: SINGLE fp16 representation (e5m10, 2^-12 input rounding), K=256 — no
// split. Frobenius-relative error model (validated against measured 4.6e-6
// for the bf16-split variant) predicts rel_err ~1.9e-4 < 1e-3.
// 3x fewer HMMA than the bf16-split kernels -> HMMA-limited ~58 us.
// Structure = proven R8: 128x128 CTA tile, 4 warps (64x64), 3-stage cp.async,
// one barrier per chunk, triangle tiles + mirrored write via smem transpose.
// ============================================================================

#define NROWS  8192
#define DIM    256
#define KCH    64            // fp16 per K-chunk (128 B rows)
#define NCHUNK 4             // K = 256
#define TILE   128

// fp16 normalized features: 8192 x 256 = 4 MB scratch.
__device__ __align__(128) __half g_X[(size_t)NROWS * DIM];

// ---------------------------------------------------------------------------
__device__ __forceinline__ uint32_t smem_u32(const void* p) {
    uint32_t a;
    asm("{ .reg .u64 t; cvta.to.shared.u64 t, %1; cvt.u32.u64 %0, t; }"
        : "=r"(a) : "l"(p));
    return a;
}

#define CP_ASYNC_16(dst, src) \
    asm volatile("cp.async.cg.shared.global [%0], [%1], 16;" \
                 :: "r"(dst), "l"(src) : "memory")
#define CP_ASYNC_COMMIT() \
    asm volatile("cp.async.commit_group;" ::: "memory")
#define CP_ASYNC_WAIT(n) \
    asm volatile("cp.async.wait_group %0;" :: "n"(n) : "memory")

__device__ __forceinline__ void ldsm4(uint32_t* r, uint32_t addr) {
    asm volatile("ldmatrix.sync.aligned.m8n8.x4.shared.b16 {%0,%1,%2,%3}, [%4];"
                 : "=r"(r[0]), "=r"(r[1]), "=r"(r[2]), "=r"(r[3]) : "r"(addr));
}

__device__ __forceinline__ void mma16816(float* d, const uint32_t* a,
                                         const uint32_t* b) {
    asm volatile(
        "mma.sync.aligned.m16n8k16.row.col.f32.f16.f16.f32 "
        "{%0,%1,%2,%3}, {%4,%5,%6,%7}, {%8,%9}, {%0,%1,%2,%3};"
        : "+f"(d[0]), "+f"(d[1]), "+f"(d[2]), "+f"(d[3])
        : "r"(a[0]), "r"(a[1]), "r"(a[2]), "r"(a[3]), "r"(b[0]), "r"(b[1]));
}

// ---------------------------------------------------------------------------
// Kernel 1: normalize rows, emit fp16. One warp per row.
// ---------------------------------------------------------------------------
__global__ void __launch_bounds__(256)
norm_f16_kernel(const float* __restrict__ feats)
{
    const int row  = blockIdx.x * 8 + (threadIdx.x >> 5);
    const int lane = threadIdx.x & 31;

    const float4* src = reinterpret_cast<const float4*>(feats + (size_t)row * DIM);
    float4 v0 = src[lane * 2];
    float4 v1 = src[lane * 2 + 1];

    float ss = v0.x * v0.x + v0.y * v0.y + v0.z * v0.z + v0.w * v0.w
             + v1.x * v1.x + v1.y * v1.y + v1.z * v1.z + v1.w * v1.w;
    #pragma unroll
    for (int o = 16; o; o >>= 1)
        ss += __shfl_xor_sync(0xFFFFFFFFu, ss, o);

    const float inv = 1.0f / fmaxf(sqrtf(ss), 1e-8f);

    float vals[8] = {v0.x, v0.y, v0.z, v0.w, v1.x, v1.y, v1.z, v1.w};
    const size_t base = (size_t)row * DIM;
    #pragma unroll
    for (int j = 0; j < 8; ++j) {
        const int c = lane * 8 + j;
        g_X[base + c] = __float2half_rn(vals[j] * inv);
    }
}

// ---------------------------------------------------------------------------
// Kernel 2: 128x128 CTA tile, 4 warps (64x64 each), 3 stages, 128 threads.
// smem per stage 32 KB; x3 = 96 KB. Mirror buffer 66 KB reuses stage smem.
// 2 CTAs/SM.
// ---------------------------------------------------------------------------
#define SMEM_STAGE_SZ 32768
#define SMEM_B_OFF    16384
#define SMEM_TOTAL    98304

__global__ void __launch_bounds__(128, 2)
cosine_gemm_kernel(float* __restrict__ out)
{
    extern __shared__ char smem[];
    const uint32_t sbase = smem_u32(smem);
    const int tid  = threadIdx.x;
    const int lane = tid & 31;
    const int wid  = tid >> 5;       // 0..3

    // Triangular tile decode: t -> (by, bx), bx <= by
    const int t = blockIdx.x;
    int by = (int)((sqrtf(8.0f * (float)t + 1.0f) - 1.0f) * 0.5f);
    while ((by + 1) * (by + 2) / 2 <= t) ++by;
    while (by * (by + 1) / 2 > t) --by;
    const int bx = t - by * (by + 1) / 2;

    const int rowbase = by * TILE;   // M rows (A operand)
    const int colbase = bx * TILE;   // N cols (B operand)

    const int wm = (wid >> 1) * 64;  // warp tile origin in M (0, 64)
    const int wn = (wid & 1) * 64;   // warp tile origin in N (0, 64)

    // --- cp.async loader: A 8 + B 8 groups of 16B per thread -------------
    const int lr = tid >> 3;         // 0..15
    const int lc = tid & 7;          // 0..7

    auto issue = [&](int kc) {
        const uint32_t stg = (uint32_t)(kc % 3) * SMEM_STAGE_SZ;
        #pragma unroll
        for (int p = 0; p < 8; ++p) {
            const int row = p * 16 + lr;
            const uint32_t swc = (uint32_t)((lc ^ (row & 7)) * 16);
            CP_ASYNC_16(sbase + stg + row * 128 + swc,
                &g_X[(size_t)(rowbase + row) * DIM + kc * KCH + lc * 8]);
            CP_ASYNC_16(sbase + stg + SMEM_B_OFF + row * 128 + swc,
                &g_X[(size_t)(colbase + row) * DIM + kc * KCH + lc * 8]);
        }
        CP_ASYNC_COMMIT();
    };

    // Fragment loaders (one s-step worth).
    auto load_afr = [&](uint32_t aB, int s, uint32_t (*afr)[4]) {
        #pragma unroll
        for (int i = 0; i < 4; ++i) {
            const int row = wm + 16 * i + (lane & 15);
            const int ch  = s * 2 + (lane >> 4);
            ldsm4(afr[i], aB + row * 128 + ((ch ^ (row & 7)) * 16));
        }
    };
    auto load_bfr = [&](uint32_t bB, int s, uint32_t (*bfr)[4]) {
        #pragma unroll
        for (int jj = 0; jj < 4; ++jj) {
            const int row = wn + 16 * jj + ((lane >> 4) << 3) + (lane & 7);
            const int ch  = s * 2 + ((lane >> 3) & 1);
            ldsm4(bfr[jj], bB + row * 128 + ((ch ^ (row & 7)) * 16));
        }
    };

    float acc[4][8][4];
    #pragma unroll
    for (int i = 0; i < 4; ++i)
        #pragma unroll
        for (int j = 0; j < 8; ++j)
            #pragma unroll
            for (int r = 0; r < 4; ++r)
                acc[i][j][r] = 0.0f;

    uint32_t afr[2][4][4];
    uint32_t bfr[2][4][4];

    issue(0);
    issue(1);

    for (int kc = 0; kc < NCHUNK; ++kc) {
        if (kc == NCHUNK - 1) { CP_ASYNC_WAIT(0); } else { CP_ASYNC_WAIT(1); }
        __syncthreads();
        // Stage (kc+2)%3 readers all passed the barrier above (they ran in
        // chunk kc-1): WAR-safe, and loads overlap compute.
        if (kc + 2 < NCHUNK) issue(kc + 2);

        const uint32_t aB = sbase + (uint32_t)(kc % 3) * SMEM_STAGE_SZ;
        const uint32_t bB = aB + SMEM_B_OFF;

        // Software-pipelined fragments: load s+1 while computing s.
        load_afr(aB, 0, afr[0]);
        load_bfr(bB, 0, bfr[0]);
        #pragma unroll
        for (int s = 0; s < 4; ++s) {
            if (s < 3) {
                load_afr(aB, s + 1, afr[(s + 1) & 1]);
                load_bfr(bB, s + 1, bfr[(s + 1) & 1]);
            }
            #pragma unroll
            for (int i = 0; i < 4; ++i)
                #pragma unroll
                for (int j = 0; j < 8; ++j)
                    mma16816(acc[i][j], afr[s & 1][i],
                             &bfr[s & 1][j >> 1][(j & 1) * 2]);
        }
    }

    // --- Epilogue ---------------------------------------------------------
    const int grp = lane >> 2;       // 0..7
    const int t4  = lane & 3;        // 0..3

    // Direct write from registers (float2 = full 32B sector per quad).
    #pragma unroll
    for (int i = 0; i < 4; ++i) {
        #pragma unroll
        for (int j = 0; j < 8; ++j) {
            const size_t gr = (size_t)(rowbase + wm + 16 * i + grp);
            const size_t gc = (size_t)(colbase + wn + 8 * j + t4 * 2);
            float2 v01 = make_float2(fmaxf(acc[i][j][0], 0.0f),
                                     fmaxf(acc[i][j][1], 0.0f));
            float2 v23 = make_float2(fmaxf(acc[i][j][2], 0.0f),
                                     fmaxf(acc[i][j][3], 0.0f));
            *reinterpret_cast<float2*>(&out[gr * NROWS + gc]) = v01;
            *reinterpret_cast<float2*>(&out[(gr + 8) * NROWS + gc]) = v23;
        }
    }

    // Mirror write via smem transpose (skip on diagonal tiles).
    if (bx != by) {
        float* ctile = reinterpret_cast<float*>(smem);   // [128][129]
        __syncthreads();   // mainloop smem reads complete
        #pragma unroll
        for (int i = 0; i < 4; ++i) {
            #pragma unroll
            for (int j = 0; j < 8; ++j) {
                const int m = wm + 16 * i + grp;
                const int n = wn + 8 * j + t4 * 2;
                ctile[m * 129 + n]           = fmaxf(acc[i][j][0], 0.0f);
                ctile[m * 129 + n + 1]       = fmaxf(acc[i][j][1], 0.0f);
                ctile[(m + 8) * 129 + n]     = fmaxf(acc[i][j][2], 0.0f);
                ctile[(m + 8) * 129 + n + 1] = fmaxf(acc[i][j][3], 0.0f);
            }
        }
        __syncthreads();
        // warp w: n = w*32 .. w*32+31 ; stride-129 column reads conflict-free
        #pragma unroll
        for (int rr = 0; rr < 32; ++rr) {
            const int n = wid * 32 + rr;
            #pragma unroll
            for (int q = 0; q < 4; ++q) {
                const int m = q * 32 + lane;
                out[(size_t)(colbase + n) * NROWS + rowbase + m] =
                    ctile[m * 129 + n];
            }
        }
    }
}

// ---------------------------------------------------------------------------
extern "C" void kernel_launch(void* const* d_in, const int* in_sizes, int n_in,
                              void* d_out, int out_size)
{
    const float* feats = (const float*)d_in[0];
    float* out = (float*)d_out;
    (void)in_sizes; (void)n_in; (void)out_size;

    cudaFuncSetAttribute(cosine_gemm_kernel,
                         cudaFuncAttributeMaxDynamicSharedMemorySize,
                         SMEM_TOTAL);

    norm_f16_kernel<<<NROWS / 8, 256>>>(feats);

    const int ntiles = (NROWS / TILE) * (NROWS / TILE + 1) / 2;   // 2080
    cosine_gemm_kernel<<<ntiles, 128, SMEM_TOTAL>>>(out);
}

// round 12
// speedup vs baseline: 1.8761x; 1.0027x over previous
#include <cuda_runtime.h>
#include <cuda_fp16.h>
#include <cstdint>

// ============================================================================
// sim = clamp(xn @ xn.T, 0), xn = row-normalized features (8192 x 256 fp32)
//
// sm_100 SIMT mma path is MAC-rate capped (~0.22 HMMA.16816/cyc/SM, measured
// invariant across schedules). Only lever: fewer MACs.
// R11: SINGLE fp16 representation (e5m10, 2^-12 input rounding), K=256 — no
// split. Frobenius-relative error model (validated against measured 4.6e-6
// for the bf16-split variant) predicts rel_err ~1.9e-4 < 1e-3.
// 3x fewer HMMA than the bf16-split kernels -> HMMA-limited ~58 us.
// Structure = proven R8: 128x128 CTA tile, 4 warps (64x64), 3-stage cp.async,
// one barrier per chunk, triangle tiles + mirrored write via smem transpose.
// ============================================================================

#define NROWS  8192
#define DIM    256
#define KCH    64            // fp16 per K-chunk (128 B rows)
#define NCHUNK 4             // K = 256
#define TILE   128

// fp16 normalized features: 8192 x 256 = 4 MB scratch.
__device__ __align__(128) __half g_X[(size_t)NROWS * DIM];

// ---------------------------------------------------------------------------
__device__ __forceinline__ uint32_t smem_u32(const void* p) {
    uint32_t a;
    asm("{ .reg .u64 t; cvta.to.shared.u64 t, %1; cvt.u32.u64 %0, t; }"
        : "=r"(a) : "l"(p));
    return a;
}

#define CP_ASYNC_16(dst, src) \
    asm volatile("cp.async.cg.shared.global [%0], [%1], 16;" \
                 :: "r"(dst), "l"(src) : "memory")
#define CP_ASYNC_COMMIT() \
    asm volatile("cp.async.commit_group;" ::: "memory")
#define CP_ASYNC_WAIT(n) \
    asm volatile("cp.async.wait_group %0;" :: "n"(n) : "memory")

__device__ __forceinline__ void ldsm4(uint32_t* r, uint32_t addr) {
    asm volatile("ldmatrix.sync.aligned.m8n8.x4.shared.b16 {%0,%1,%2,%3}, [%4];"
                 : "=r"(r[0]), "=r"(r[1]), "=r"(r[2]), "=r"(r[3]) : "r"(addr));
}

__device__ __forceinline__ void mma16816(float* d, const uint32_t* a,
                                         const uint32_t* b) {
    asm volatile(
        "mma.sync.aligned.m16n8k16.row.col.f32.f16.f16.f32 "
        "{%0,%1,%2,%3}, {%4,%5,%6,%7}, {%8,%9}, {%0,%1,%2,%3};"
        : "+f"(d[0]), "+f"(d[1]), "+f"(d[2]), "+f"(d[3])
        : "r"(a[0]), "r"(a[1]), "r"(a[2]), "r"(a[3]), "r"(b[0]), "r"(b[1]));
}

// ---------------------------------------------------------------------------
// Kernel 1: normalize rows, emit fp16. One warp per row.
// ---------------------------------------------------------------------------
__global__ void __launch_bounds__(256)
norm_f16_kernel(const float* __restrict__ feats)
{
    const int row  = blockIdx.x * 8 + (threadIdx.x >> 5);
    const int lane = threadIdx.x & 31;

    const float4* src = reinterpret_cast<const float4*>(feats + (size_t)row * DIM);
    float4 v0 = src[lane * 2];
    float4 v1 = src[lane * 2 + 1];

    float ss = v0.x * v0.x + v0.y * v0.y + v0.z * v0.z + v0.w * v0.w
             + v1.x * v1.x + v1.y * v1.y + v1.z * v1.z + v1.w * v1.w;
    #pragma unroll
    for (int o = 16; o; o >>= 1)
        ss += __shfl_xor_sync(0xFFFFFFFFu, ss, o);

    const float inv = 1.0f / fmaxf(sqrtf(ss), 1e-8f);

    float vals[8] = {v0.x, v0.y, v0.z, v0.w, v1.x, v1.y, v1.z, v1.w};
    const size_t base = (size_t)row * DIM;
    #pragma unroll
    for (int j = 0; j < 8; ++j) {
        const int c = lane * 8 + j;
        g_X[base + c] = __float2half_rn(vals[j] * inv);
    }
}

// ---------------------------------------------------------------------------
// Kernel 2: 128x128 CTA tile, 4 warps (64x64 each), 3 stages, 128 threads.
// smem per stage 32 KB; x3 = 96 KB. Mirror buffer 66 KB reuses stage smem.
// 2 CTAs/SM.
// ---------------------------------------------------------------------------
#define SMEM_STAGE_SZ 32768
#define SMEM_B_OFF    16384
#define SMEM_TOTAL    98304

__global__ void __launch_bounds__(128, 2)
cosine_gemm_kernel(float* __restrict__ out)
{
    extern __shared__ char smem[];
    const uint32_t sbase = smem_u32(smem);
    const int tid  = threadIdx.x;
    const int lane = tid & 31;
    const int wid  = tid >> 5;       // 0..3

    // Triangular tile decode: t -> (by, bx), bx <= by
    const int t = blockIdx.x;
    int by = (int)((sqrtf(8.0f * (float)t + 1.0f) - 1.0f) * 0.5f);
    while ((by + 1) * (by + 2) / 2 <= t) ++by;
    while (by * (by + 1) / 2 > t) --by;
    const int bx = t - by * (by + 1) / 2;

    const int rowbase = by * TILE;   // M rows (A operand)
    const int colbase = bx * TILE;   // N cols (B operand)

    const int wm = (wid >> 1) * 64;  // warp tile origin in M (0, 64)
    const int wn = (wid & 1) * 64;   // warp tile origin in N (0, 64)

    // --- cp.async loader: A 8 + B 8 groups of 16B per thread -------------
    const int lr = tid >> 3;         // 0..15
    const int lc = tid & 7;          // 0..7

    auto issue = [&](int kc) {
        const uint32_t stg = (uint32_t)(kc % 3) * SMEM_STAGE_SZ;
        #pragma unroll
        for (int p = 0; p < 8; ++p) {
            const int row = p * 16 + lr;
            const uint32_t swc = (uint32_t)((lc ^ (row & 7)) * 16);
            CP_ASYNC_16(sbase + stg + row * 128 + swc,
                &g_X[(size_t)(rowbase + row) * DIM + kc * KCH + lc * 8]);
            CP_ASYNC_16(sbase + stg + SMEM_B_OFF + row * 128 + swc,
                &g_X[(size_t)(colbase + row) * DIM + kc * KCH + lc * 8]);
        }
        CP_ASYNC_COMMIT();
    };

    // Fragment loaders (one s-step worth).
    auto load_afr = [&](uint32_t aB, int s, uint32_t (*afr)[4]) {
        #pragma unroll
        for (int i = 0; i < 4; ++i) {
            const int row = wm + 16 * i + (lane & 15);
            const int ch  = s * 2 + (lane >> 4);
            ldsm4(afr[i], aB + row * 128 + ((ch ^ (row & 7)) * 16));
        }
    };
    auto load_bfr = [&](uint32_t bB, int s, uint32_t (*bfr)[4]) {
        #pragma unroll
        for (int jj = 0; jj < 4; ++jj) {
            const int row = wn + 16 * jj + ((lane >> 4) << 3) + (lane & 7);
            const int ch  = s * 2 + ((lane >> 3) & 1);
            ldsm4(bfr[jj], bB + row * 128 + ((ch ^ (row & 7)) * 16));
        }
    };

    float acc[4][8][4];
    #pragma unroll
    for (int i = 0; i < 4; ++i)
        #pragma unroll
        for (int j = 0; j < 8; ++j)
            #pragma unroll
            for (int r = 0; r < 4; ++r)
                acc[i][j][r] = 0.0f;

    uint32_t afr[2][4][4];
    uint32_t bfr[2][4][4];

    issue(0);
    issue(1);

    for (int kc = 0; kc < NCHUNK; ++kc) {
        if (kc == NCHUNK - 1) { CP_ASYNC_WAIT(0); } else { CP_ASYNC_WAIT(1); }
        __syncthreads();
        // Stage (kc+2)%3 readers all passed the barrier above (they ran in
        // chunk kc-1): WAR-safe, and loads overlap compute.
        if (kc + 2 < NCHUNK) issue(kc + 2);

        const uint32_t aB = sbase + (uint32_t)(kc % 3) * SMEM_STAGE_SZ;
        const uint32_t bB = aB + SMEM_B_OFF;

        // Software-pipelined fragments: load s+1 while computing s.
        load_afr(aB, 0, afr[0]);
        load_bfr(bB, 0, bfr[0]);
        #pragma unroll
        for (int s = 0; s < 4; ++s) {
            if (s < 3) {
                load_afr(aB, s + 1, afr[(s + 1) & 1]);
                load_bfr(bB, s + 1, bfr[(s + 1) & 1]);
            }
            #pragma unroll
            for (int i = 0; i < 4; ++i)
                #pragma unroll
                for (int j = 0; j < 8; ++j)
                    mma16816(acc[i][j], afr[s & 1][i],
                             &bfr[s & 1][j >> 1][(j & 1) * 2]);
        }
    }

    // --- Epilogue ---------------------------------------------------------
    const int grp = lane >> 2;       // 0..7
    const int t4  = lane & 3;        // 0..3

    // Direct write from registers (float2 = full 32B sector per quad).
    #pragma unroll
    for (int i = 0; i < 4; ++i) {
        #pragma unroll
        for (int j = 0; j < 8; ++j) {
            const size_t gr = (size_t)(rowbase + wm + 16 * i + grp);
            const size_t gc = (size_t)(colbase + wn + 8 * j + t4 * 2);
            float2 v01 = make_float2(fmaxf(acc[i][j][0], 0.0f),
                                     fmaxf(acc[i][j][1], 0.0f));
            float2 v23 = make_float2(fmaxf(acc[i][j][2], 0.0f),
                                     fmaxf(acc[i][j][3], 0.0f));
            *reinterpret_cast<float2*>(&out[gr * NROWS + gc]) = v01;
            *reinterpret_cast<float2*>(&out[(gr + 8) * NROWS + gc]) = v23;
        }
    }

    // Mirror write via smem transpose (skip on diagonal tiles).
    if (bx != by) {
        float* ctile = reinterpret_cast<float*>(smem);   // [128][129]
        __syncthreads();   // mainloop smem reads complete
        #pragma unroll
        for (int i = 0; i < 4; ++i) {
            #pragma unroll
            for (int j = 0; j < 8; ++j) {
                const int m = wm + 16 * i + grp;
                const int n = wn + 8 * j + t4 * 2;
                ctile[m * 129 + n]           = fmaxf(acc[i][j][0], 0.0f);
                ctile[m * 129 + n + 1]       = fmaxf(acc[i][j][1], 0.0f);
                ctile[(m + 8) * 129 + n]     = fmaxf(acc[i][j][2], 0.0f);
                ctile[(m + 8) * 129 + n + 1] = fmaxf(acc[i][j][3], 0.0f);
            }
        }
        __syncthreads();
        // warp w: n = w*32 .. w*32+31 ; stride-129 column reads conflict-free
        #pragma unroll
        for (int rr = 0; rr < 32; ++rr) {
            const int n = wid * 32 + rr;
            #pragma unroll
            for (int q = 0; q < 4; ++q) {
                const int m = q * 32 + lane;
                out[(size_t)(colbase + n) * NROWS + rowbase + m] =
                    ctile[m * 129 + n];
            }
        }
    }
}

// ---------------------------------------------------------------------------
extern "C" void kernel_launch(void* const* d_in, const int* in_sizes, int n_in,
                              void* d_out, int out_size)
{
    const float* feats = (const float*)d_in[0];
    float* out = (float*)d_out;
    (void)in_sizes; (void)n_in; (void)out_size;

    cudaFuncSetAttribute(cosine_gemm_kernel,
                         cudaFuncAttributeMaxDynamicSharedMemorySize,
                         SMEM_TOTAL);

    norm_f16_kernel<<<NROWS / 8, 256>>>(feats);

    const int ntiles = (NROWS / TILE) * (NROWS / TILE + 1) / 2;   // 2080
    cosine_gemm_kernel<<<ntiles, 128, SMEM_TOTAL>>>(out);
}

// round 15
// speedup vs baseline: 2.2509x; 1.1998x over previous
#include <cuda_runtime.h>
#include <cuda_fp16.h>
#include <cstdint>

// ============================================================================
// sim = clamp(xn @ xn.T, 0), xn = row-normalized features (8192 x 256 fp32)
//
// R13 = R12 (fp16 single-precision path, K=256, 128x128 CTA tile, 4 warps of
// 64x64, 3-stage cp.async, one barrier per chunk, triangle tiles) with ONE
// change: the mirrored tile is written DIRECTLY from registers (scattered
// STG.32 -- 4 fully-covered 32B sectors per instruction), eliminating the
// smem-transpose round trip (256 KB L1 traffic per tile) and two barriers.
// ============================================================================

#define NROWS  8192
#define DIM    256
#define KCH    64            // fp16 per K-chunk (128 B rows)
#define NCHUNK 4             // K = 256
#define TILE   128

// fp16 normalized features: 8192 x 256 = 4 MB scratch.
__device__ __align__(128) __half g_X[(size_t)NROWS * DIM];

// ---------------------------------------------------------------------------
__device__ __forceinline__ uint32_t smem_u32(const void* p) {
    uint32_t a;
    asm("{ .reg .u64 t; cvta.to.shared.u64 t, %1; cvt.u32.u64 %0, t; }"
        : "=r"(a) : "l"(p));
    return a;
}

#define CP_ASYNC_16(dst, src) \
    asm volatile("cp.async.cg.shared.global [%0], [%1], 16;" \
                 :: "r"(dst), "l"(src) : "memory")
#define CP_ASYNC_COMMIT() \
    asm volatile("cp.async.commit_group;" ::: "memory")
#define CP_ASYNC_WAIT(n) \
    asm volatile("cp.async.wait_group %0;" :: "n"(n) : "memory")

__device__ __forceinline__ void ldsm4(uint32_t* r, uint32_t addr) {
    asm volatile("ldmatrix.sync.aligned.m8n8.x4.shared.b16 {%0,%1,%2,%3}, [%4];"
                 : "=r"(r[0]), "=r"(r[1]), "=r"(r[2]), "=r"(r[3]) : "r"(addr));
}

__device__ __forceinline__ void mma16816(float* d, const uint32_t* a,
                                         const uint32_t* b) {
    asm volatile(
        "mma.sync.aligned.m16n8k16.row.col.f32.f16.f16.f32 "
        "{%0,%1,%2,%3}, {%4,%5,%6,%7}, {%8,%9}, {%0,%1,%2,%3};"
        : "+f"(d[0]), "+f"(d[1]), "+f"(d[2]), "+f"(d[3])
        : "r"(a[0]), "r"(a[1]), "r"(a[2]), "r"(a[3]), "r"(b[0]), "r"(b[1]));
}

// ---------------------------------------------------------------------------
// Kernel 1: normalize rows, emit fp16. One warp per row.
// ---------------------------------------------------------------------------
__global__ void __launch_bounds__(256)
norm_f16_kernel(const float* __restrict__ feats)
{
    const int row  = blockIdx.x * 8 + (threadIdx.x >> 5);
    const int lane = threadIdx.x & 31;

    const float4* src = reinterpret_cast<const float4*>(feats + (size_t)row * DIM);
    float4 v0 = src[lane * 2];
    float4 v1 = src[lane * 2 + 1];

    float ss = v0.x * v0.x + v0.y * v0.y + v0.z * v0.z + v0.w * v0.w
             + v1.x * v1.x + v1.y * v1.y + v1.z * v1.z + v1.w * v1.w;
    #pragma unroll
    for (int o = 16; o; o >>= 1)
        ss += __shfl_xor_sync(0xFFFFFFFFu, ss, o);

    const float inv = 1.0f / fmaxf(sqrtf(ss), 1e-8f);

    float vals[8] = {v0.x, v0.y, v0.z, v0.w, v1.x, v1.y, v1.z, v1.w};
    const size_t base = (size_t)row * DIM;
    #pragma unroll
    for (int j = 0; j < 8; ++j) {
        const int c = lane * 8 + j;
        g_X[base + c] = __float2half_rn(vals[j] * inv);
    }
}

// ---------------------------------------------------------------------------
// Kernel 2: 128x128 CTA tile, 4 warps (64x64 each), 3 stages, 128 threads.
// smem: 3 x 32 KB stages = 96 KB. 2 CTAs/SM.
// ---------------------------------------------------------------------------
#define SMEM_STAGE_SZ 32768
#define SMEM_B_OFF    16384
#define SMEM_TOTAL    98304

__global__ void __launch_bounds__(128, 2)
cosine_gemm_kernel(float* __restrict__ out)
{
    extern __shared__ char smem[];
    const uint32_t sbase = smem_u32(smem);
    const int tid  = threadIdx.x;
    const int lane = tid & 31;
    const int wid  = tid >> 5;       // 0..3

    // Triangular tile decode: t -> (by, bx), bx <= by
    const int t = blockIdx.x;
    int by = (int)((sqrtf(8.0f * (float)t + 1.0f) - 1.0f) * 0.5f);
    while ((by + 1) * (by + 2) / 2 <= t) ++by;
    while (by * (by + 1) / 2 > t) --by;
    const int bx = t - by * (by + 1) / 2;

    const int rowbase = by * TILE;   // M rows (A operand)
    const int colbase = bx * TILE;   // N cols (B operand)

    const int wm = (wid >> 1) * 64;  // warp tile origin in M (0, 64)
    const int wn = (wid & 1) * 64;   // warp tile origin in N (0, 64)

    // --- cp.async loader: A 8 + B 8 groups of 16B per thread -------------
    const int lr = tid >> 3;         // 0..15
    const int lc = tid & 7;          // 0..7

    auto issue = [&](int kc) {
        const uint32_t stg = (uint32_t)(kc % 3) * SMEM_STAGE_SZ;
        #pragma unroll
        for (int p = 0; p < 8; ++p) {
            const int row = p * 16 + lr;
            const uint32_t swc = (uint32_t)((lc ^ (row & 7)) * 16);
            CP_ASYNC_16(sbase + stg + row * 128 + swc,
                &g_X[(size_t)(rowbase + row) * DIM + kc * KCH + lc * 8]);
            CP_ASYNC_16(sbase + stg + SMEM_B_OFF + row * 128 + swc,
                &g_X[(size_t)(colbase + row) * DIM + kc * KCH + lc * 8]);
        }
        CP_ASYNC_COMMIT();
    };

    // Fragment loaders (one s-step worth).
    auto load_afr = [&](uint32_t aB, int s, uint32_t (*afr)[4]) {
        #pragma unroll
        for (int i = 0; i < 4; ++i) {
            const int row = wm + 16 * i + (lane & 15);
            const int ch  = s * 2 + (lane >> 4);
            ldsm4(afr[i], aB + row * 128 + ((ch ^ (row & 7)) * 16));
        }
    };
    auto load_bfr = [&](uint32_t bB, int s, uint32_t (*bfr)[4]) {
        #pragma unroll
        for (int jj = 0; jj < 4; ++jj) {
            const int row = wn + 16 * jj + ((lane >> 4) << 3) + (lane & 7);
            const int ch  = s * 2 + ((lane >> 3) & 1);
            ldsm4(bfr[jj], bB + row * 128 + ((ch ^ (row & 7)) * 16));
        }
    };

    float acc[4][8][4];
    #pragma unroll
    for (int i = 0; i < 4; ++i)
        #pragma unroll
        for (int j = 0; j < 8; ++j)
            #pragma unroll
            for (int r = 0; r < 4; ++r)
                acc[i][j][r] = 0.0f;

    uint32_t afr[2][4][4];
    uint32_t bfr[2][4][4];

    issue(0);
    issue(1);

    for (int kc = 0; kc < NCHUNK; ++kc) {
        if (kc == NCHUNK - 1) { CP_ASYNC_WAIT(0); } else { CP_ASYNC_WAIT(1); }
        __syncthreads();
        // Stage (kc+2)%3 readers all passed the barrier above (they ran in
        // chunk kc-1): WAR-safe, and loads overlap compute.
        if (kc + 2 < NCHUNK) issue(kc + 2);

        const uint32_t aB = sbase + (uint32_t)(kc % 3) * SMEM_STAGE_SZ;
        const uint32_t bB = aB + SMEM_B_OFF;

        // Software-pipelined fragments: load s+1 while computing s.
        load_afr(aB, 0, afr[0]);
        load_bfr(bB, 0, bfr[0]);
        #pragma unroll
        for (int s = 0; s < 4; ++s) {
            if (s < 3) {
                load_afr(aB, s + 1, afr[(s + 1) & 1]);
                load_bfr(bB, s + 1, bfr[(s + 1) & 1]);
            }
            #pragma unroll
            for (int i = 0; i < 4; ++i)
                #pragma unroll
                for (int j = 0; j < 8; ++j)
                    mma16816(acc[i][j], afr[s & 1][i],
                             &bfr[s & 1][j >> 1][(j & 1) * 2]);
        }
    }

    // --- Epilogue (no smem, no barriers) ----------------------------------
    const int grp = lane >> 2;       // 0..7
    const int t4  = lane & 3;        // 0..3
    const bool mirror = (bx != by);

    #pragma unroll
    for (int i = 0; i < 4; ++i) {
        #pragma unroll
        for (int j = 0; j < 8; ++j) {
            const float c0 = fmaxf(acc[i][j][0], 0.0f);
            const float c1 = fmaxf(acc[i][j][1], 0.0f);
            const float c2 = fmaxf(acc[i][j][2], 0.0f);
            const float c3 = fmaxf(acc[i][j][3], 0.0f);

            const size_t gr = (size_t)(rowbase + wm + 16 * i + grp);
            const size_t gc = (size_t)(colbase + wn + 8 * j + t4 * 2);

            // Direct tile: float2 = full 32B sector per quad.
            *reinterpret_cast<float2*>(&out[gr * NROWS + gc]) =
                make_float2(c0, c1);
            *reinterpret_cast<float2*>(&out[(gr + 8) * NROWS + gc]) =
                make_float2(c2, c3);

            // Mirrored tile straight from registers. Per STG.32, warp lanes
            // cover 4 rows (t4) x 8 consecutive floats (grp) = 4 full 32B
            // sectors -- 100% sector efficiency, zero smem traffic.
            if (mirror) {
                out[gc * NROWS + gr]             = c0;
                out[(gc + 1) * NROWS + gr]       = c1;
                out[gc * NROWS + gr + 8]         = c2;
                out[(gc + 1) * NROWS + gr + 8]   = c3;
            }
        }
    }
}

// ---------------------------------------------------------------------------
extern "C" void kernel_launch(void* const* d_in, const int* in_sizes, int n_in,
                              void* d_out, int out_size)
{
    const float* feats = (const float*)d_in[0];
    float* out = (float*)d_out;
    (void)in_sizes; (void)n_in; (void)out_size;

    cudaFuncSetAttribute(cosine_gemm_kernel,
                         cudaFuncAttributeMaxDynamicSharedMemorySize,
                         SMEM_TOTAL);

    norm_f16_kernel<<<NROWS / 8, 256>>>(feats);

    const int ntiles = (NROWS / TILE) * (NROWS / TILE + 1) / 2;   // 2080
    cosine_gemm_kernel<<<ntiles, 128, SMEM_TOTAL>>>(out);
}